// round 7
// baseline (speedup 1.0000x reference)
#include <cuda_runtime.h>
#include <cuda_fp16.h>
#include <cstdint>
#include <math.h>

#define BB 8
#define SS 512
#define DD 256
#define NPAIRS (SS * (SS - 1) / 2)   // 130816
#define TILE 64
#define NT (SS / TILE)               // 8
#define NTRI (NT * (NT + 1) / 2)     // 36 lower-tri 64x64 tiles per batch

// ---------------------------------------------------------------------------
__device__ __forceinline__ uint32_t smem_u32(const void* p) {
    uint32_t a;
    asm("{ .reg .u64 t; cvta.to.shared.u64 t, %1; cvt.u32.u64 %0, t; }" : "=r"(a) : "l"(p));
    return a;
}
__device__ __forceinline__ void ldm_x4(uint32_t& r0, uint32_t& r1, uint32_t& r2, uint32_t& r3,
                                       uint32_t addr) {
    asm volatile("ldmatrix.sync.aligned.m8n8.x4.shared.b16 {%0,%1,%2,%3}, [%4];"
                 : "=r"(r0), "=r"(r1), "=r"(r2), "=r"(r3) : "r"(addr));
}
__device__ __forceinline__ void mma_f16(float* d, const uint32_t* a, const uint32_t* bfr) {
    asm volatile(
        "mma.sync.aligned.m16n8k16.row.col.f32.f16.f16.f32 "
        "{%0,%1,%2,%3}, {%4,%5,%6,%7}, {%8,%9}, {%0,%1,%2,%3};"
        : "+f"(d[0]), "+f"(d[1]), "+f"(d[2]), "+f"(d[3])
        : "r"(a[0]), "r"(a[1]), "r"(a[2]), "r"(a[3]), "r"(bfr[0]), "r"(bfr[1]));
}
__device__ __forceinline__ void sts128(uint32_t addr, uint32_t a, uint32_t b,
                                       uint32_t c, uint32_t d) {
    asm volatile("st.shared.v4.b32 [%0], {%1,%2,%3,%4};"
                 :: "r"(addr), "r"(a), "r"(b), "r"(c), "r"(d) : "memory");
}

// ---------------------------------------------------------------------------
// Fused kernel: one 64x64 Gram tile per CTA, 8 warps (4m x 2n, warp 16x32).
// Phase 1: load 128 rows of fp32 x (32 LDG.128/thread), convert fp16 into
//          swizzled smem tiles (512B rows, XOR-16B swizzle), exact fp32 norms
//          via pairwise shfl. Diagonal tiles alias B tile to A tile.
// Phase 2: 16 register-pipelined ldmatrix/mma.sync fp16->fp32 ks-steps.
// Phase 3: d = sqrt(max(ni + nj - 2*dot, eps)), strict-lower-tri stores.
// smem: norms[128] f32, A 32KB, B 32KB -> 65.5KB, 3 CTAs/SM.
// ---------------------------------------------------------------------------
#define SM_TILE 512
#define MAT_BYTES 32768              // 64 rows x 512B (256 fp16)
#define SMEM_TOTAL (SM_TILE + 2 * MAT_BYTES)

__global__ __launch_bounds__(256) void dist_kernel(const float* __restrict__ x,
                                                   float* __restrict__ out) {
    extern __shared__ char smem[];
    uint32_t sbase = smem_u32(smem);
    int tid = threadIdx.x;
    int lane = tid & 31;
    int wid = tid >> 5;
    int wm = wid >> 1;   // 0..3 -> m offset 16*wm
    int wn = wid & 1;    // 0..1 -> n offset 32*wn

    int b = blockIdx.y;
    int t = blockIdx.x;
    int ti = 0;
    while ((ti + 1) * (ti + 2) / 2 <= t) ti++;
    int tj = t - ti * (ti + 1) / 2;
    bool diag = (ti == tj);

    float* nrm = reinterpret_cast<float*>(smem);   // [0..63]=i rows, [64..127]=j rows

    // ---- Phase 1: load fp32, convert to fp16 smem tiles, exact norms ----
    {
        int row = tid >> 1;          // 0..127 (0-63 A, 64-127 B)
        int half = tid & 1;          // k half: 128 floats each
        bool isB = row >= 64;
        int lrow = row & 63;
        if (!(diag && isB)) {
            int srcRow = b * SS + (isB ? tj : ti) * TILE + lrow;
            const float4* src = reinterpret_cast<const float4*>(x + (size_t)srcRow * DD)
                                + half * 32;
            uint32_t rbase = sbase + SM_TILE + (isB ? MAT_BYTES : 0) + lrow * 512;
            float ns = 0.0f;
#pragma unroll
            for (int p = 0; p < 16; ++p) {
                float4 v0 = src[2 * p];
                float4 v1 = src[2 * p + 1];
                ns += v0.x * v0.x + v0.y * v0.y + v0.z * v0.z + v0.w * v0.w
                    + v1.x * v1.x + v1.y * v1.y + v1.z * v1.z + v1.w * v1.w;
                __half2 h0 = __floats2half2_rn(v0.x, v0.y);
                __half2 h1 = __floats2half2_rn(v0.z, v0.w);
                __half2 h2 = __floats2half2_rn(v1.x, v1.y);
                __half2 h3 = __floats2half2_rn(v1.z, v1.w);
                int slot = half * 16 + p;
                uint32_t addr = rbase + ((slot ^ (lrow & 7)) * 16);
                sts128(addr, *(uint32_t*)&h0, *(uint32_t*)&h1,
                             *(uint32_t*)&h2, *(uint32_t*)&h3);
            }
            ns += __shfl_xor_sync(0xFFFFFFFFu, ns, 1);
            if (half == 0) nrm[row] = ns;
        }
    }
    __syncthreads();

    // ---- Phase 2: MMA mainloop (16 ks-steps over K=256) ----
    int rA = lane & 15;
    int kselA = (lane >> 4) & 1;
    int rB = (lane & 7) | ((lane >> 1) & 8);
    int kselB = (lane >> 3) & 1;
    uint32_t aRow = sbase + SM_TILE + (wm * 16 + rA) * 512;
    uint32_t bRow = sbase + SM_TILE + (diag ? 0 : MAT_BYTES) + (wn * 32 + rB) * 512;

    float acc[4][4];
#pragma unroll
    for (int nt = 0; nt < 4; ++nt)
#pragma unroll
        for (int e = 0; e < 4; ++e) acc[nt][e] = 0.0f;

    uint32_t afr[2][4], bfr[2][2][4];
    auto load_frags = [&](int p, int ks) {
        uint32_t swA = ((ks * 2 + kselA) ^ (rA & 7)) * 16;
        uint32_t swB = ((ks * 2 + kselB) ^ (rB & 7)) * 16;
        ldm_x4(afr[p][0], afr[p][1], afr[p][2], afr[p][3], aRow + swA);
#pragma unroll
        for (int nh = 0; nh < 2; ++nh)
            ldm_x4(bfr[p][nh][0], bfr[p][nh][1], bfr[p][nh][2], bfr[p][nh][3],
                   bRow + nh * 8192 + swB);
    };
    auto do_mma = [&](int p) {
#pragma unroll
        for (int nt = 0; nt < 4; ++nt) {
            uint32_t bb2[2] = { bfr[p][nt >> 1][(nt & 1) * 2],
                                bfr[p][nt >> 1][(nt & 1) * 2 + 1] };
            mma_f16(acc[nt], afr[p], bb2);
        }
    };

    load_frags(0, 0);
#pragma unroll
    for (int ks = 0; ks < 16; ++ks) {
        if (ks < 15) load_frags((ks + 1) & 1, ks + 1);
        do_mma(ks & 1);
    }

    // ---- Phase 3: epilogue ----
    const float* si = nrm;
    const float* sjn = nrm + (diag ? 0 : 64);
    int lr = lane >> 2;            // 0..7
    int lc = 2 * (lane & 3);       // 0,2,4,6
    float* ob = out + (size_t)b * NPAIRS;
    {
        int r0 = wm * 16 + lr;
        int i0 = ti * TILE + r0;
        int i1 = i0 + 8;
        float n0 = si[r0], n1 = si[r0 + 8];
        int base0 = i0 * (i0 - 1) / 2;
        int base1 = i1 * (i1 - 1) / 2;
#pragma unroll
        for (int nt = 0; nt < 4; ++nt) {
            int col = wn * 32 + nt * 8 + lc;
            int j = tj * TILE + col;
            float njc0 = sjn[col], njc1 = sjn[col + 1];
            float* c = acc[nt];
            if (j < i0)     ob[base0 + j]     = sqrtf(fmaxf(n0 + njc0 - 2.0f * c[0], 1e-7f));
            if (j + 1 < i0) ob[base0 + j + 1] = sqrtf(fmaxf(n0 + njc1 - 2.0f * c[1], 1e-7f));
            if (j < i1)     ob[base1 + j]     = sqrtf(fmaxf(n1 + njc0 - 2.0f * c[2], 1e-7f));
            if (j + 1 < i1) ob[base1 + j + 1] = sqrtf(fmaxf(n1 + njc1 - 2.0f * c[3], 1e-7f));
        }
    }
}

// ---------------------------------------------------------------------------
extern "C" void kernel_launch(void* const* d_in, const int* in_sizes, int n_in,
                              void* d_out, int out_size) {
    const float* x = (const float*)d_in[0];
    float* out = (float*)d_out;

    static bool attr_done = false;
    if (!attr_done) {
        cudaFuncSetAttribute(dist_kernel, cudaFuncAttributeMaxDynamicSharedMemorySize,
                             SMEM_TOTAL);
        attr_done = true;
    }

    dim3 grid(NTRI, BB);
    dist_kernel<<<grid, 256, SMEM_TOTAL>>>(x, out);
}

// round 9
// speedup vs baseline: 1.7247x; 1.7247x over previous
#include <cuda_runtime.h>
#include <cuda_fp16.h>
#include <cstdint>
#include <math.h>

#define BB 8
#define SS 512
#define DD 256
#define NPAIRS (SS * (SS - 1) / 2)   // 130816
#define TILE 64
#define NTRI 36                      // lower-tri 64x64 tiles per batch
#define NPAIRT 18                    // tile pairs per batch (2 tiles per CTA)

// ---- device globals (no cudaMalloc allowed) ----
__device__ float g_norms[BB * SS];
__device__ __align__(16) __half g_h[BB * SS * DD];   // fp16(x), 2MB

// tile index LUT: (ti<<4)|tj for t in [0,36)  -- 36 entries
__device__ const uint8_t c_tij[NTRI] = {
    0x00,
    0x10, 0x11,
    0x20, 0x21, 0x22,
    0x30, 0x31, 0x32, 0x33,
    0x40, 0x41, 0x42, 0x43, 0x44,
    0x50, 0x51, 0x52, 0x53, 0x54, 0x55,
    0x60, 0x61, 0x62, 0x63, 0x64, 0x65, 0x66,
    0x70, 0x71, 0x72, 0x73, 0x74, 0x75, 0x76, 0x77
};

// ---------------------------------------------------------------------------
__device__ __forceinline__ uint32_t smem_u32(const void* p) {
    uint32_t a;
    asm("{ .reg .u64 t; cvta.to.shared.u64 t, %1; cvt.u32.u64 %0, t; }" : "=r"(a) : "l"(p));
    return a;
}
__device__ __forceinline__ void cp_async16(uint32_t dst, const void* src) {
    asm volatile("cp.async.cg.shared.global [%0], [%1], 16;" :: "r"(dst), "l"(src) : "memory");
}
__device__ __forceinline__ void cp_commit() { asm volatile("cp.async.commit_group;" ::: "memory"); }
__device__ __forceinline__ void ldm_x4(uint32_t& r0, uint32_t& r1, uint32_t& r2, uint32_t& r3,
                                       uint32_t addr) {
    asm volatile("ldmatrix.sync.aligned.m8n8.x4.shared.b16 {%0,%1,%2,%3}, [%4];"
                 : "=r"(r0), "=r"(r1), "=r"(r2), "=r"(r3) : "r"(addr));
}
__device__ __forceinline__ void mma_f16(float* d, const uint32_t* a, const uint32_t* bfr) {
    asm volatile(
        "mma.sync.aligned.m16n8k16.row.col.f32.f16.f16.f32 "
        "{%0,%1,%2,%3}, {%4,%5,%6,%7}, {%8,%9}, {%0,%1,%2,%3};"
        : "+f"(d[0]), "+f"(d[1]), "+f"(d[2]), "+f"(d[3])
        : "r"(a[0]), "r"(a[1]), "r"(a[2]), "r"(a[3]), "r"(bfr[0]), "r"(bfr[1]));
}

// ---------------------------------------------------------------------------
// Kernel 1: per-row norms (exact fp32) + fp16 conversion. One warp per row.
// ---------------------------------------------------------------------------
__global__ __launch_bounds__(256) void prep_kernel(const float* __restrict__ x) {
    int row = blockIdx.x * 8 + (threadIdx.x >> 5);
    int lane = threadIdx.x & 31;
    if (row >= BB * SS) return;
    const float4* x4 = reinterpret_cast<const float4*>(x) + (size_t)row * (DD / 4);
    float4 a = x4[lane];
    float4 c = x4[lane + 32];
    float s = a.x * a.x + a.y * a.y + a.z * a.z + a.w * a.w
            + c.x * c.x + c.y * c.y + c.z * c.z + c.w * c.w;
#pragma unroll
    for (int o = 16; o; o >>= 1) s += __shfl_xor_sync(0xFFFFFFFFu, s, o);
    if (lane == 0) g_norms[row] = s;

    size_t base = (size_t)row * DD;
#pragma unroll
    for (int g = 0; g < 2; ++g) {
        float4 v = g ? c : a;
        __half2 h0 = __floats2half2_rn(v.x, v.y);
        __half2 h1 = __floats2half2_rn(v.z, v.w);
        uint2 hv = make_uint2(*(uint32_t*)&h0, *(uint32_t*)&h1);
        *reinterpret_cast<uint2*>(g_h + base + g * 128 + lane * 4) = hv;
    }
}

// ---------------------------------------------------------------------------
// Kernel 2: TWO 64x64 Gram tiles per CTA (tiles t and t+18) -> grid 144 CTAs
// = one wave. 8 warps (4m x 2n, warp tile 16x32). Full-K tiles (512B rows,
// XOR-16B swizzle), cp.async issued for BOTH tiles up front in separate
// commit groups: tile1's load latency hides behind tile0's compute.
// fp32-accumulate mma.sync (verified numerics). Diag tiles alias B -> A.
// smem: norms 1KB + 2 x (A 32KB + B 32KB) = 129.5KB -> 1 CTA/SM.
// ---------------------------------------------------------------------------
#define SM_NORM 1024
#define TBUF_BYTES 65536             // A(64x512B) + B(64x512B)
#define SMEM_TOTAL (SM_NORM + 2 * TBUF_BYTES)

__global__ __launch_bounds__(256) void dist_kernel(float* __restrict__ out) {
    extern __shared__ char smem[];
    uint32_t sbase = smem_u32(smem);
    int tid = threadIdx.x;
    int lane = tid & 31;
    int wid = tid >> 5;
    int wm = wid >> 1;   // 0..3 -> m offset 16*wm
    int wn = wid & 1;    // 0..1 -> n offset 32*wn
    int b = blockIdx.y;

    int tij0 = c_tij[blockIdx.x];
    int tij1 = c_tij[blockIdx.x + NPAIRT];

    // ---- norms for both tiles: nrm[0..63]=si0, [64..127]=sj0, [128..191]=si1, [192..255]=sj1
    float* nrm = reinterpret_cast<float*>(smem);
    {
        int p = tid >> 7;            // tile 0/1
        int half = (tid >> 6) & 1;   // si / sj
        int r = tid & 63;
        int tt = p ? tij1 : tij0;
        int blk = half ? (tt & 15) : (tt >> 4);
        nrm[tid] = g_norms[b * SS + blk * TILE + r];
    }

    // ---- issue full-K loads for both tiles (separate commit groups) ----
    int kk = tid & 31, row8 = tid >> 5;   // warp reads one 512B row contiguously
    auto issue_tile = [&](int tij, uint32_t tbase) {
        int ti = tij >> 4, tj = tij & 15;
        bool diag = (ti == tj);
        const __half* aSrc = g_h + ((size_t)(b * SS + ti * TILE)) * DD;
        const __half* bSrc = g_h + ((size_t)(b * SS + tj * TILE)) * DD;
#pragma unroll
        for (int q = 0; q < 16; ++q) {
            int row = row8 + 8 * q;      // 0..127 (A rows 0-63, B rows 64-127)
            bool isB = row >= 64;
            int lr = row & 63;
            if (!(diag && isB)) {
                const __half* src = (isB ? bSrc : aSrc) + (size_t)lr * DD + kk * 8;
                uint32_t dst = tbase + (isB ? 32768u : 0u) + lr * 512 + ((kk ^ (lr & 7)) * 16);
                cp_async16(dst, src);
            }
        }
        cp_commit();
    };
    uint32_t base0 = sbase + SM_NORM;
    uint32_t base1 = base0 + TBUF_BYTES;
    issue_tile(tij0, base0);
    issue_tile(tij1, base1);

    // ---- per-lane ldmatrix addressing (512B rows, 32 x 16B slots) ----
    int rA = lane & 15;
    int kselA = (lane >> 4) & 1;
    int rB = (lane & 7) | ((lane >> 1) & 8);
    int kselB = (lane >> 3) & 1;

    float* ob = out + (size_t)b * NPAIRS;
    int lr = lane >> 2;            // 0..7
    int lc = 2 * (lane & 3);       // 0,2,4,6

    auto compute_tile = [&](int tij, uint32_t tbase, const float* si, const float* sjn) {
        int ti = tij >> 4, tj = tij & 15;
        bool diag = (ti == tj);
        uint32_t aRow = tbase + (wm * 16 + rA) * 512;
        uint32_t bRow = tbase + (diag ? 0 : 32768) + (wn * 32 + rB) * 512;

        float acc[4][4];
#pragma unroll
        for (int nt = 0; nt < 4; ++nt)
#pragma unroll
            for (int e = 0; e < 4; ++e) acc[nt][e] = 0.0f;

        uint32_t afr[2][4], bfr[2][2][4];
        auto load_frags = [&](int p, int ks) {
            uint32_t swA = ((ks * 2 + kselA) ^ (rA & 7)) * 16;
            uint32_t swB = ((ks * 2 + kselB) ^ (rB & 7)) * 16;
            ldm_x4(afr[p][0], afr[p][1], afr[p][2], afr[p][3], aRow + swA);
#pragma unroll
            for (int nh = 0; nh < 2; ++nh)
                ldm_x4(bfr[p][nh][0], bfr[p][nh][1], bfr[p][nh][2], bfr[p][nh][3],
                       bRow + nh * 8192 + swB);
        };
        auto do_mma = [&](int p) {
#pragma unroll
            for (int nt = 0; nt < 4; ++nt) {
                uint32_t bb2[2] = { bfr[p][nt >> 1][(nt & 1) * 2],
                                    bfr[p][nt >> 1][(nt & 1) * 2 + 1] };
                mma_f16(acc[nt], afr[p], bb2);
            }
        };

        load_frags(0, 0);
#pragma unroll
        for (int ks = 0; ks < 16; ++ks) {
            if (ks < 15) load_frags((ks + 1) & 1, ks + 1);
            do_mma(ks & 1);
        }

        // epilogue
        int r0 = wm * 16 + lr;
        int i0 = ti * TILE + r0;
        int i1 = i0 + 8;
        float n0 = si[r0], n1 = si[r0 + 8];
        int bs0 = i0 * (i0 - 1) / 2;
        int bs1 = i1 * (i1 - 1) / 2;
#pragma unroll
        for (int nt = 0; nt < 4; ++nt) {
            int col = wn * 32 + nt * 8 + lc;
            int j = tj * TILE + col;
            float njc0 = sjn[col], njc1 = sjn[col + 1];
            float* c = acc[nt];
            if (j < i0)     ob[bs0 + j]     = sqrtf(fmaxf(n0 + njc0 - 2.0f * c[0], 1e-7f));
            if (j + 1 < i0) ob[bs0 + j + 1] = sqrtf(fmaxf(n0 + njc1 - 2.0f * c[1], 1e-7f));
            if (j < i1)     ob[bs1 + j]     = sqrtf(fmaxf(n1 + njc0 - 2.0f * c[2], 1e-7f));
            if (j + 1 < i1) ob[bs1 + j + 1] = sqrtf(fmaxf(n1 + njc1 - 2.0f * c[3], 1e-7f));
        }
    };

    // tile 0 ready (group for tile1 still pending)
    asm volatile("cp.async.wait_group 1;" ::: "memory");
    __syncthreads();
    compute_tile(tij0, base0, nrm, nrm + 64);

    // tile 1 ready
    asm volatile("cp.async.wait_group 0;" ::: "memory");
    __syncthreads();
    compute_tile(tij1, base1, nrm + 128, nrm + 192);
}

// ---------------------------------------------------------------------------
extern "C" void kernel_launch(void* const* d_in, const int* in_sizes, int n_in,
                              void* d_out, int out_size) {
    const float* x = (const float*)d_in[0];
    float* out = (float*)d_out;

    static bool attr_done = false;
    if (!attr_done) {
        cudaFuncSetAttribute(dist_kernel, cudaFuncAttributeMaxDynamicSharedMemorySize,
                             SMEM_TOTAL);
        attr_done = true;
    }

    prep_kernel<<<512, 256>>>(x);

    dim3 grid(NPAIRT, BB);
    dist_kernel<<<grid, 256, SMEM_TOTAL>>>(out);
}